// round 13
// baseline (speedup 1.0000x reference)
#include <cuda_runtime.h>
#include <cuda_bf16.h>

// Problem constants (fixed shapes from reference)
#define NN 50000
#define NE 800000
#define DD 96
#define D4 (DD / 4)   // 24 float4 per row

#define SCAN_B 1024
#define SCAN_NB ((NN + SCAN_B - 1) / SCAN_B)   // 49

// fused-kernel dynamic smem: xs[64][96] + ws[96][96]
#define XS_FLOATS (64 * DD)
#define WS_FLOATS (DD * DD)
#define FUSED_SMEM ((XS_FLOATS + WS_FLOATS) * 4)   // 61440 bytes

// ---- device scratch (no runtime allocation allowed) ----
__device__ int   g_deg[NN];
__device__ float g_dinv[NN];
__device__ int   g_rowptr[NN + 1];
__device__ int   g_cursor[NN];
__device__ int   g_col[NE];
__device__ int   g_partial[SCAN_NB];
__device__ int   g_is64;          // 1 if edge_index is int64, 0 if int32
__device__ float g_hp[NN * DD];   // layer-1 output (post bias+PReLU)

// ---------------------------------------------------------------------------
// init: degree = 1 (self loop). Block 0 additionally detects edge dtype.
// ---------------------------------------------------------------------------
__global__ void k_init(const void* __restrict__ ei_raw) {
    int i = blockIdx.x * blockDim.x + threadIdx.x;
    if (i < NN) g_deg[i] = 1;

    if (blockIdx.x == 0) {
        __shared__ int bad;
        if (threadIdx.x == 0) bad = 0;
        __syncthreads();
        const long long* p64 = (const long long*)ei_raw;
        int stride = NE / (256 * 64);   // 16K probes
        int myBad = 0;
        for (int j = 0; j < 64; j++) {
            int e = (threadIdx.x * 64 + j) * stride;
            if (e < NE) {
                long long v = p64[e];
                if (v < 0 || v >= NN) myBad = 1;
            }
        }
        if (myBad) atomicOr(&bad, 1);
        __syncthreads();
        if (threadIdx.x == 0) g_is64 = bad ? 0 : 1;
    }
}

__device__ __forceinline__ void load_edge(const void* ei_raw, int e, int& s, int& d) {
    if (g_is64) {
        const long long* p = (const long long*)ei_raw;
        s = (int)p[e];
        d = (int)p[NE + e];
    } else {
        const int* p = (const int*)ei_raw;
        s = p[e];
        d = p[NE + e];
    }
}

// ---------------------------------------------------------------------------
// degree count
// ---------------------------------------------------------------------------
__global__ void k_count_deg(const void* __restrict__ ei_raw) {
    int e = blockIdx.x * blockDim.x + threadIdx.x;
    if (e < NE) {
        int s, d;
        load_edge(ei_raw, e, s, d);
        if ((unsigned)d < NN) atomicAdd(&g_deg[d], 1);
    }
}

// ---------------------------------------------------------------------------
// fused: per-block sum of (deg-1) for scan, plus dinv = rsqrt(deg)
// ---------------------------------------------------------------------------
__global__ void k_scanpartial_dinv() {
    __shared__ int s[SCAN_B];
    int i = blockIdx.x * SCAN_B + threadIdx.x;
    int dg = (i < NN) ? g_deg[i] : 1;
    if (i < NN) g_dinv[i] = rsqrtf((float)dg);
    int v = (i < NN) ? (dg - 1) : 0;
    s[threadIdx.x] = v;
    __syncthreads();
    for (int off = SCAN_B / 2; off > 0; off >>= 1) {
        if (threadIdx.x < off) s[threadIdx.x] += s[threadIdx.x + off];
        __syncthreads();
    }
    if (threadIdx.x == 0) g_partial[blockIdx.x] = s[0];
}

// ---------------------------------------------------------------------------
// scan_final with INLINE cross-block offset: warp 0 masked-sums the partials
// of preceding blocks (49 values) -> no separate offsets kernel needed.
// ---------------------------------------------------------------------------
__global__ void k_scan_final() {
    __shared__ int s[SCAN_B];
    __shared__ int sbase;
    int bid = blockIdx.x;

    if (threadIdx.x < 32) {
        int lane = threadIdx.x;
        int v0 = (lane < bid) ? g_partial[lane] : 0;                 // lane < bid <= 48
        int v1 = (32 + lane < bid) ? g_partial[32 + lane] : 0;
        int t = v0 + v1;
#pragma unroll
        for (int off = 16; off > 0; off >>= 1)
            t += __shfl_down_sync(0xffffffffu, t, off);
        if (lane == 0) sbase = t;
    }

    int i = bid * SCAN_B + threadIdx.x;
    int v = (i < NN) ? (g_deg[i] - 1) : 0;
    s[threadIdx.x] = v;
    __syncthreads();
    for (int off = 1; off < SCAN_B; off <<= 1) {
        int t = 0;
        if ((int)threadIdx.x >= off) t = s[threadIdx.x - off];
        __syncthreads();
        s[threadIdx.x] += t;
        __syncthreads();
    }
    int inc = s[threadIdx.x];
    int base = sbase;
    if (i < NN) {
        g_rowptr[i] = base + inc - v;
        g_cursor[i] = base + inc - v;
    }
    if (i == NN - 1) g_rowptr[NN] = base + inc;
}

// ---------------------------------------------------------------------------
// CSR fill
// ---------------------------------------------------------------------------
__global__ void k_fill(const void* __restrict__ ei_raw) {
    int e = blockIdx.x * blockDim.x + threadIdx.x;
    if (e < NE) {
        int s, d;
        load_edge(ei_raw, e, s, d);
        if ((unsigned)d < NN && (unsigned)s < NN) {
            int pos = atomicAdd(&g_cursor[d], 1);
            if ((unsigned)pos < NE) g_col[pos] = s;
        }
    }
}

// ---------------------------------------------------------------------------
// FUSED LAYER:  out = act( (Dinv*A*Dinv @ Xin) @ W + b )
//  - cp.async preloads FULL W (36.8KB) into smem at kernel start, overlapped
//    with phase-1 aggregation; phase 2 then runs with W resident: ONE sync,
//    no mid-GEMM barriers, no W refetch.
//  - Phase 1: warp w aggregates 8 nodes into xs (float4 gathers, shfl bcast).
//  - Phase 2: xs[64][96] @ ws[96][96], bias+PReLU epilogue.
// Xin == nullptr -> read g_hp; outp == nullptr -> write g_hp.
// ---------------------------------------------------------------------------
__global__ void __launch_bounds__(256, 3)
k_fused(const float* __restrict__ Xin,
        const float* __restrict__ W,
        const float* __restrict__ bias,
        const float* __restrict__ a1,
        int use_prelu,
        float* __restrict__ outp) {
    extern __shared__ float smem_f[];
    float (*xs)[DD] = (float(*)[DD])smem_f;               // 24 KB
    float (*ws)[DD] = (float(*)[DD])(smem_f + XS_FLOATS); // 36.8 KB

    const float4* x4 = (Xin != nullptr) ? (const float4*)Xin : (const float4*)g_hp;
    float* dst = (outp != nullptr) ? outp : (float*)g_hp;

    int row0 = blockIdx.x * 64;
    int tid  = threadIdx.x;
    int warp = tid >> 5;
    int lane = tid & 31;
    bool activeF = lane < D4;        // 24 lanes carry the 96 features

    // ---- kick off async W load (2304 float4, 9 per thread) ----
    {
        const float4* W4 = (const float4*)W;
        unsigned ws_base = (unsigned)__cvta_generic_to_shared(ws);
#pragma unroll
        for (int i = 0; i < 9; i++) {
            int idx = tid + i * 256;
            asm volatile("cp.async.ca.shared.global [%0], [%1], 16;\n"
                         :: "r"(ws_base + idx * 16), "l"(W4 + idx));
        }
        asm volatile("cp.async.commit_group;\n");
    }

    // ---------------- Phase 1: aggregate 8 nodes per warp ----------------
#pragma unroll 1
    for (int r = 0; r < 8; r++) {
        int node = row0 + warp * 8 + r;
        float4 acc = make_float4(0.f, 0.f, 0.f, 0.f);
        if (node < NN) {
            float di = g_dinv[node];
            if (activeF) {
                float4 v = x4[node * D4 + lane];
                acc.x = di * v.x; acc.y = di * v.y;
                acc.z = di * v.z; acc.w = di * v.w;
            }
            int beg = g_rowptr[node];
            int end = g_rowptr[node + 1];
            for (int base = beg; base < end; base += 32) {
                int e = base + lane;
                int s = 0;
                float ns = 0.f;
                if (e < end) {
                    s = g_col[e];
                    ns = g_dinv[s];
                }
                int cnt = min(32, end - base);
                int j = 0;
                for (; j + 4 <= cnt; j += 4) {
                    int   s0 = __shfl_sync(0xffffffffu, s,  j + 0);
                    int   s1 = __shfl_sync(0xffffffffu, s,  j + 1);
                    int   s2 = __shfl_sync(0xffffffffu, s,  j + 2);
                    int   s3 = __shfl_sync(0xffffffffu, s,  j + 3);
                    float n0 = __shfl_sync(0xffffffffu, ns, j + 0);
                    float n1 = __shfl_sync(0xffffffffu, ns, j + 1);
                    float n2 = __shfl_sync(0xffffffffu, ns, j + 2);
                    float n3 = __shfl_sync(0xffffffffu, ns, j + 3);
                    if (activeF) {
                        float4 v0 = x4[s0 * D4 + lane];
                        float4 v1 = x4[s1 * D4 + lane];
                        float4 v2 = x4[s2 * D4 + lane];
                        float4 v3 = x4[s3 * D4 + lane];
                        acc.x = fmaf(n0, v0.x, acc.x); acc.y = fmaf(n0, v0.y, acc.y);
                        acc.z = fmaf(n0, v0.z, acc.z); acc.w = fmaf(n0, v0.w, acc.w);
                        acc.x = fmaf(n1, v1.x, acc.x); acc.y = fmaf(n1, v1.y, acc.y);
                        acc.z = fmaf(n1, v1.z, acc.z); acc.w = fmaf(n1, v1.w, acc.w);
                        acc.x = fmaf(n2, v2.x, acc.x); acc.y = fmaf(n2, v2.y, acc.y);
                        acc.z = fmaf(n2, v2.z, acc.z); acc.w = fmaf(n2, v2.w, acc.w);
                        acc.x = fmaf(n3, v3.x, acc.x); acc.y = fmaf(n3, v3.y, acc.y);
                        acc.z = fmaf(n3, v3.z, acc.z); acc.w = fmaf(n3, v3.w, acc.w);
                    }
                }
                for (; j < cnt; j++) {
                    int   sj = __shfl_sync(0xffffffffu, s,  j);
                    float nj = __shfl_sync(0xffffffffu, ns, j);
                    if (activeF) {
                        float4 v = x4[sj * D4 + lane];
                        acc.x = fmaf(nj, v.x, acc.x); acc.y = fmaf(nj, v.y, acc.y);
                        acc.z = fmaf(nj, v.z, acc.z); acc.w = fmaf(nj, v.w, acc.w);
                    }
                }
            }
            acc.x *= di; acc.y *= di; acc.z *= di; acc.w *= di;
        }
        if (activeF)
            *(float4*)&xs[warp * 8 + r][lane * 4] = acc;
    }

    // wait for W + close phase 1 (single barrier for the whole kernel body)
    asm volatile("cp.async.wait_group 0;\n");
    __syncthreads();

    // ---------------- Phase 2: xs[64][96] @ ws[96][96] ----------------
    int tx = lane;
    int ty = warp;

    float acc[8][3];
#pragma unroll
    for (int r = 0; r < 8; r++) { acc[r][0] = 0.f; acc[r][1] = 0.f; acc[r][2] = 0.f; }

#pragma unroll 1
    for (int kb = 0; kb < DD; kb += 32) {
#pragma unroll
        for (int k4 = 0; k4 < 32; k4 += 4) {
            float4 xv[8];
#pragma unroll
            for (int r = 0; r < 8; r++)
                xv[r] = *(const float4*)&xs[ty * 8 + r][kb + k4];
#pragma unroll
            for (int kk = 0; kk < 4; kk++) {
                float w0 = ws[kb + k4 + kk][tx];
                float w1 = ws[kb + k4 + kk][tx + 32];
                float w2 = ws[kb + k4 + kk][tx + 64];
#pragma unroll
                for (int r = 0; r < 8; r++) {
                    float xvk = (kk == 0) ? xv[r].x :
                                (kk == 1) ? xv[r].y :
                                (kk == 2) ? xv[r].z : xv[r].w;
                    acc[r][0] = fmaf(xvk, w0, acc[r][0]);
                    acc[r][1] = fmaf(xvk, w1, acc[r][1]);
                    acc[r][2] = fmaf(xvk, w2, acc[r][2]);
                }
            }
        }
    }

    // epilogue: bias + optional PReLU, store
    float b0 = bias[tx], b1 = bias[tx + 32], b2 = bias[tx + 64];
    float a = use_prelu ? a1[0] : 0.f;
#pragma unroll
    for (int r = 0; r < 8; r++) {
        int gr = row0 + ty * 8 + r;
        if (gr < NN) {
            float v0 = acc[r][0] + b0;
            float v1 = acc[r][1] + b1;
            float v2 = acc[r][2] + b2;
            if (use_prelu) {
                v0 = v0 > 0.f ? v0 : a * v0;
                v1 = v1 > 0.f ? v1 : a * v1;
                v2 = v2 > 0.f ? v2 : a * v2;
            }
            dst[gr * DD + tx]      = v0;
            dst[gr * DD + tx + 32] = v1;
            dst[gr * DD + tx + 64] = v2;
        }
    }
}

// ---------------------------------------------------------------------------
extern "C" void kernel_launch(void* const* d_in, const int* in_sizes, int n_in,
                              void* d_out, int out_size) {
    const float* x  = (const float*)d_in[0];
    const void*  ei = (const void*)d_in[1];
    const float* W1 = (const float*)d_in[2];
    const float* b1 = (const float*)d_in[3];
    const float* a1 = (const float*)d_in[4];
    const float* W2 = (const float*)d_in[5];
    const float* b2 = (const float*)d_in[6];
    float*       out = (float*)d_out;

    // opt-in to 61.4 KB dynamic smem (host-side, idempotent, capture-safe)
    (void)cudaFuncSetAttribute(k_fused,
                               cudaFuncAttributeMaxDynamicSharedMemorySize,
                               FUSED_SMEM);

    int fusedGrid = (NN + 63) / 64;   // 782

    // ---- graph structure prep (5 launches) ----
    k_init<<<(NN + 255) / 256, 256>>>(ei);
    k_count_deg<<<(NE + 255) / 256, 256>>>(ei);
    k_scanpartial_dinv<<<SCAN_NB, SCAN_B>>>();
    k_scan_final<<<SCAN_NB, SCAN_B>>>();        // inline cross-block offsets
    k_fill<<<(NE + 255) / 256, 256>>>(ei);

    // ---- layer 1: g_hp = PReLU( (Anorm @ x) @ W1 + b1 ) ----
    k_fused<<<fusedGrid, 256, FUSED_SMEM>>>(x, W1, b1, a1, 1, nullptr);

    // ---- layer 2: out = (Anorm @ g_hp) @ W2 + b2 ----
    k_fused<<<fusedGrid, 256, FUSED_SMEM>>>(nullptr, W2, b2, a1, 0, out);
}

// round 14
// speedup vs baseline: 1.0807x; 1.0807x over previous
#include <cuda_runtime.h>
#include <cuda_bf16.h>

// Problem constants (fixed shapes from reference)
#define NN 50000
#define NE 800000
#define DD 96
#define D4 (DD / 4)   // 24 float4 per row

#define SCAN_B 1024
#define SCAN_NB ((NN + SCAN_B - 1) / SCAN_B)   // 49

// fused-kernel dynamic smem: xs[64][96] + ws[96][96]
#define XS_FLOATS (64 * DD)
#define WS_FLOATS (DD * DD)
#define FUSED_SMEM ((XS_FLOATS + WS_FLOATS) * 4)   // 61440 bytes

// ---- device scratch (no runtime allocation allowed) ----
// g_deg holds pure in-edge counts. It is zero on first use (.bss) and is
// re-zeroed by k_fill each call, so every replay starts from zero.
__device__ int   g_deg[NN];
__device__ float g_dinv[NN];
__device__ int   g_rowptr[NN + 1];
__device__ int   g_cursor[NN];
__device__ int   g_col[NE];
__device__ float g_hp[NN * DD];   // layer-1 output (post bias+PReLU)

// ---------------------------------------------------------------------------
// Block-local edge-dtype vote: every active thread probes int64-slot e
// (e < NE -> byte offset < 8*NE, in-bounds for BOTH int32 and int64 buffers).
// int32 data interpreted as int64 packs two indices -> out of [0,NN) unless
// the odd element is 0 (p = 2e-5); a 256-probe block vote cannot misfire.
// ---------------------------------------------------------------------------
__device__ __forceinline__ int block_is64(const void* ei_raw, int e) {
    const long long* p64 = (const long long*)ei_raw;
    int bad = 0;
    if (e < NE) {
        long long v = p64[e];
        if (v < 0 || v >= NN) bad = 1;
    }
    return !__syncthreads_or(bad);
}

// ---------------------------------------------------------------------------
// degree count (dst half only)
// ---------------------------------------------------------------------------
__global__ void k_count(const void* __restrict__ ei_raw) {
    int e = blockIdx.x * blockDim.x + threadIdx.x;
    int is64 = block_is64(ei_raw, e);
    if (e < NE) {
        int d = is64 ? (int)((const long long*)ei_raw)[NE + e]
                     : ((const int*)ei_raw)[NE + e];
        if ((unsigned)d < NN) atomicAdd(&g_deg[d], 1);
    }
}

// ---------------------------------------------------------------------------
// single-kernel scan: block b sums counts of all preceding indices itself
// (<=48 loads/thread), then does an in-block inclusive scan.
// Also computes dinv = rsqrt(count+1). g_deg is READ-ONLY here.
// ---------------------------------------------------------------------------
__global__ void k_scan() {
    __shared__ int s[SCAN_B];
    __shared__ int sbase;
    int bid = blockIdx.x;
    int tid = threadIdx.x;

    // preceding-block sum
    int pre = 0;
    for (int i = tid; i < bid * SCAN_B; i += SCAN_B) pre += g_deg[i];
    s[tid] = pre;
    __syncthreads();
    for (int off = SCAN_B / 2; off > 0; off >>= 1) {
        if (tid < off) s[tid] += s[tid + off];
        __syncthreads();
    }
    if (tid == 0) sbase = s[0];
    __syncthreads();

    int i = bid * SCAN_B + tid;
    int c = (i < NN) ? g_deg[i] : 0;
    if (i < NN) g_dinv[i] = rsqrtf((float)(c + 1));   // +1 = self loop
    s[tid] = c;
    __syncthreads();
    for (int off = 1; off < SCAN_B; off <<= 1) {
        int t = 0;
        if (tid >= off) t = s[tid - off];
        __syncthreads();
        s[tid] += t;
        __syncthreads();
    }
    int inc = s[tid];
    if (i < NN) {
        g_rowptr[i] = sbase + inc - c;
        g_cursor[i] = sbase + inc - c;
    }
    if (i == NN - 1) g_rowptr[NN] = sbase + inc;
}

// ---------------------------------------------------------------------------
// CSR fill + reset g_deg for the next replay
// ---------------------------------------------------------------------------
__global__ void k_fill(const void* __restrict__ ei_raw) {
    int e = blockIdx.x * blockDim.x + threadIdx.x;
    int is64 = block_is64(ei_raw, e);
    if (e < NN) g_deg[e] = 0;                 // counts consumed; reset
    if (e < NE) {
        int s, d;
        if (is64) {
            const long long* p = (const long long*)ei_raw;
            s = (int)p[e];
            d = (int)p[NE + e];
        } else {
            const int* p = (const int*)ei_raw;
            s = p[e];
            d = p[NE + e];
        }
        if ((unsigned)d < NN && (unsigned)s < NN) {
            int pos = atomicAdd(&g_cursor[d], 1);
            if ((unsigned)pos < NE) g_col[pos] = s;
        }
    }
}

// ---------------------------------------------------------------------------
// FUSED LAYER (unchanged from round 11):  out = act( (Anorm @ Xin) @ W + b )
//  - cp.async preloads FULL W into smem, overlapped with phase-1 gather
//  - Phase 1: warp w aggregates 8 nodes into xs (float4 gathers, shfl bcast)
//  - Phase 2: xs[64][96] @ ws[96][96], bias+PReLU epilogue, ONE barrier
// Xin == nullptr -> read g_hp; outp == nullptr -> write g_hp.
// ---------------------------------------------------------------------------
__global__ void __launch_bounds__(256, 3)
k_fused(const float* __restrict__ Xin,
        const float* __restrict__ W,
        const float* __restrict__ bias,
        const float* __restrict__ a1,
        int use_prelu,
        float* __restrict__ outp) {
    extern __shared__ float smem_f[];
    float (*xs)[DD] = (float(*)[DD])smem_f;               // 24 KB
    float (*ws)[DD] = (float(*)[DD])(smem_f + XS_FLOATS); // 36.8 KB

    const float4* x4 = (Xin != nullptr) ? (const float4*)Xin : (const float4*)g_hp;
    float* dst = (outp != nullptr) ? outp : (float*)g_hp;

    int row0 = blockIdx.x * 64;
    int tid  = threadIdx.x;
    int warp = tid >> 5;
    int lane = tid & 31;
    bool activeF = lane < D4;        // 24 lanes carry the 96 features

    // ---- kick off async W load (2304 float4, 9 per thread) ----
    {
        const float4* W4 = (const float4*)W;
        unsigned ws_base = (unsigned)__cvta_generic_to_shared(ws);
#pragma unroll
        for (int i = 0; i < 9; i++) {
            int idx = tid + i * 256;
            asm volatile("cp.async.ca.shared.global [%0], [%1], 16;\n"
                         :: "r"(ws_base + idx * 16), "l"(W4 + idx));
        }
        asm volatile("cp.async.commit_group;\n");
    }

    // ---------------- Phase 1: aggregate 8 nodes per warp ----------------
#pragma unroll 1
    for (int r = 0; r < 8; r++) {
        int node = row0 + warp * 8 + r;
        float4 acc = make_float4(0.f, 0.f, 0.f, 0.f);
        if (node < NN) {
            float di = g_dinv[node];
            if (activeF) {
                float4 v = x4[node * D4 + lane];
                acc.x = di * v.x; acc.y = di * v.y;
                acc.z = di * v.z; acc.w = di * v.w;
            }
            int beg = g_rowptr[node];
            int end = g_rowptr[node + 1];
            for (int base = beg; base < end; base += 32) {
                int e = base + lane;
                int s = 0;
                float ns = 0.f;
                if (e < end) {
                    s = g_col[e];
                    ns = g_dinv[s];
                }
                int cnt = min(32, end - base);
                int j = 0;
                for (; j + 4 <= cnt; j += 4) {
                    int   s0 = __shfl_sync(0xffffffffu, s,  j + 0);
                    int   s1 = __shfl_sync(0xffffffffu, s,  j + 1);
                    int   s2 = __shfl_sync(0xffffffffu, s,  j + 2);
                    int   s3 = __shfl_sync(0xffffffffu, s,  j + 3);
                    float n0 = __shfl_sync(0xffffffffu, ns, j + 0);
                    float n1 = __shfl_sync(0xffffffffu, ns, j + 1);
                    float n2 = __shfl_sync(0xffffffffu, ns, j + 2);
                    float n3 = __shfl_sync(0xffffffffu, ns, j + 3);
                    if (activeF) {
                        float4 v0 = x4[s0 * D4 + lane];
                        float4 v1 = x4[s1 * D4 + lane];
                        float4 v2 = x4[s2 * D4 + lane];
                        float4 v3 = x4[s3 * D4 + lane];
                        acc.x = fmaf(n0, v0.x, acc.x); acc.y = fmaf(n0, v0.y, acc.y);
                        acc.z = fmaf(n0, v0.z, acc.z); acc.w = fmaf(n0, v0.w, acc.w);
                        acc.x = fmaf(n1, v1.x, acc.x); acc.y = fmaf(n1, v1.y, acc.y);
                        acc.z = fmaf(n1, v1.z, acc.z); acc.w = fmaf(n1, v1.w, acc.w);
                        acc.x = fmaf(n2, v2.x, acc.x); acc.y = fmaf(n2, v2.y, acc.y);
                        acc.z = fmaf(n2, v2.z, acc.z); acc.w = fmaf(n2, v2.w, acc.w);
                        acc.x = fmaf(n3, v3.x, acc.x); acc.y = fmaf(n3, v3.y, acc.y);
                        acc.z = fmaf(n3, v3.z, acc.z); acc.w = fmaf(n3, v3.w, acc.w);
                    }
                }
                for (; j < cnt; j++) {
                    int   sj = __shfl_sync(0xffffffffu, s,  j);
                    float nj = __shfl_sync(0xffffffffu, ns, j);
                    if (activeF) {
                        float4 v = x4[sj * D4 + lane];
                        acc.x = fmaf(nj, v.x, acc.x); acc.y = fmaf(nj, v.y, acc.y);
                        acc.z = fmaf(nj, v.z, acc.z); acc.w = fmaf(nj, v.w, acc.w);
                    }
                }
            }
            acc.x *= di; acc.y *= di; acc.z *= di; acc.w *= di;
        }
        if (activeF)
            *(float4*)&xs[warp * 8 + r][lane * 4] = acc;
    }

    // wait for W + close phase 1 (single barrier for the whole kernel body)
    asm volatile("cp.async.wait_group 0;\n");
    __syncthreads();

    // ---------------- Phase 2: xs[64][96] @ ws[96][96] ----------------
    int tx = lane;
    int ty = warp;

    float acc[8][3];
#pragma unroll
    for (int r = 0; r < 8; r++) { acc[r][0] = 0.f; acc[r][1] = 0.f; acc[r][2] = 0.f; }

#pragma unroll 1
    for (int kb = 0; kb < DD; kb += 32) {
#pragma unroll
        for (int k4 = 0; k4 < 32; k4 += 4) {
            float4 xv[8];
#pragma unroll
            for (int r = 0; r < 8; r++)
                xv[r] = *(const float4*)&xs[ty * 8 + r][kb + k4];
#pragma unroll
            for (int kk = 0; kk < 4; kk++) {
                float w0 = ws[kb + k4 + kk][tx];
                float w1 = ws[kb + k4 + kk][tx + 32];
                float w2 = ws[kb + k4 + kk][tx + 64];
#pragma unroll
                for (int r = 0; r < 8; r++) {
                    float xvk = (kk == 0) ? xv[r].x :
                                (kk == 1) ? xv[r].y :
                                (kk == 2) ? xv[r].z : xv[r].w;
                    acc[r][0] = fmaf(xvk, w0, acc[r][0]);
                    acc[r][1] = fmaf(xvk, w1, acc[r][1]);
                    acc[r][2] = fmaf(xvk, w2, acc[r][2]);
                }
            }
        }
    }

    // epilogue: bias + optional PReLU, store
    float b0 = bias[tx], b1 = bias[tx + 32], b2 = bias[tx + 64];
    float a = use_prelu ? a1[0] : 0.f;
#pragma unroll
    for (int r = 0; r < 8; r++) {
        int gr = row0 + ty * 8 + r;
        if (gr < NN) {
            float v0 = acc[r][0] + b0;
            float v1 = acc[r][1] + b1;
            float v2 = acc[r][2] + b2;
            if (use_prelu) {
                v0 = v0 > 0.f ? v0 : a * v0;
                v1 = v1 > 0.f ? v1 : a * v1;
                v2 = v2 > 0.f ? v2 : a * v2;
            }
            dst[gr * DD + tx]      = v0;
            dst[gr * DD + tx + 32] = v1;
            dst[gr * DD + tx + 64] = v2;
        }
    }
}

// ---------------------------------------------------------------------------
extern "C" void kernel_launch(void* const* d_in, const int* in_sizes, int n_in,
                              void* d_out, int out_size) {
    const float* x  = (const float*)d_in[0];
    const void*  ei = (const void*)d_in[1];
    const float* W1 = (const float*)d_in[2];
    const float* b1 = (const float*)d_in[3];
    const float* a1 = (const float*)d_in[4];
    const float* W2 = (const float*)d_in[5];
    const float* b2 = (const float*)d_in[6];
    float*       out = (float*)d_out;

    // opt-in to 61.4 KB dynamic smem (host-side, idempotent, capture-safe)
    (void)cudaFuncSetAttribute(k_fused,
                               cudaFuncAttributeMaxDynamicSharedMemorySize,
                               FUSED_SMEM);

    int fusedGrid = (NN + 63) / 64;   // 782

    // launch 0..2: prep (3 kernels)
    k_count<<<(NE + 255) / 256, 256>>>(ei);
    k_scan<<<SCAN_NB, SCAN_B>>>();
    k_fill<<<(NE + 255) / 256, 256>>>(ei);

    // launch 3 (PROFILED): layer 1  g_hp = PReLU( (Anorm @ x) @ W1 + b1 )
    k_fused<<<fusedGrid, 256, FUSED_SMEM>>>(x, W1, b1, a1, 1, nullptr);

    // launch 4: layer 2  out = (Anorm @ g_hp) @ W2 + b2
    k_fused<<<fusedGrid, 256, FUSED_SMEM>>>(nullptr, W2, b2, a1, 0, out);
}

// round 15
// speedup vs baseline: 1.1255x; 1.0415x over previous
#include <cuda_runtime.h>
#include <cuda_bf16.h>

// Problem constants (fixed shapes from reference)
#define NN 50000
#define NE 800000
#define DD 96
#define D4 (DD / 4)   // 24 float4 per row
#define K2N (DD / 2)  // 48 k-pairs

#define SCAN_B 1024
#define SCAN_NB ((NN + SCAN_B - 1) / SCAN_B)   // 49

// fused-kernel dynamic smem: xs[64][96] f32 + wsP[48][96] f32x2-packed
#define XS_FLOATS (64 * DD)
#define FUSED_SMEM (XS_FLOATS * 4 + K2N * DD * 8)   // 24576 + 36864 = 61440

#define FUSED_T 512   // 16 warps; each warp owns 4 rows

// packed f32x2 FMA: d = a*b + d (elementwise on hi/lo floats)
#define FFMA2(d, a, b) \
    asm("fma.rn.f32x2 %0, %1, %2, %0;" : "+l"(d) : "l"(a), "l"(b))

// ---- device scratch (no runtime allocation allowed) ----
// g_deg holds pure in-edge counts. Zero on first use (.bss); k_fill re-zeroes
// it each call so every graph replay starts from zero.
__device__ int   g_deg[NN];
__device__ float g_dinv[NN];
__device__ int   g_rowptr[NN + 1];
__device__ int   g_cursor[NN];
__device__ int   g_col[NE];
__device__ float g_hp[NN * DD];   // layer-1 output (post bias+PReLU)

// ---------------------------------------------------------------------------
// Block-local edge-dtype vote (int64 vs silently-int32 edge_index).
// ---------------------------------------------------------------------------
__device__ __forceinline__ int block_is64(const void* ei_raw, int e) {
    const long long* p64 = (const long long*)ei_raw;
    int bad = 0;
    if (e < NE) {
        long long v = p64[e];
        if (v < 0 || v >= NN) bad = 1;
    }
    return !__syncthreads_or(bad);
}

// ---------------------------------------------------------------------------
// degree count (dst half only)
// ---------------------------------------------------------------------------
__global__ void k_count(const void* __restrict__ ei_raw) {
    int e = blockIdx.x * blockDim.x + threadIdx.x;
    int is64 = block_is64(ei_raw, e);
    if (e < NE) {
        int d = is64 ? (int)((const long long*)ei_raw)[NE + e]
                     : ((const int*)ei_raw)[NE + e];
        if ((unsigned)d < NN) atomicAdd(&g_deg[d], 1);
    }
}

// ---------------------------------------------------------------------------
// single-kernel scan + dinv (g_deg read-only here)
// ---------------------------------------------------------------------------
__global__ void k_scan() {
    __shared__ int s[SCAN_B];
    __shared__ int sbase;
    int bid = blockIdx.x;
    int tid = threadIdx.x;

    int pre = 0;
    for (int i = tid; i < bid * SCAN_B; i += SCAN_B) pre += g_deg[i];
    s[tid] = pre;
    __syncthreads();
    for (int off = SCAN_B / 2; off > 0; off >>= 1) {
        if (tid < off) s[tid] += s[tid + off];
        __syncthreads();
    }
    if (tid == 0) sbase = s[0];
    __syncthreads();

    int i = bid * SCAN_B + tid;
    int c = (i < NN) ? g_deg[i] : 0;
    if (i < NN) g_dinv[i] = rsqrtf((float)(c + 1));   // +1 = self loop
    s[tid] = c;
    __syncthreads();
    for (int off = 1; off < SCAN_B; off <<= 1) {
        int t = 0;
        if (tid >= off) t = s[tid - off];
        __syncthreads();
        s[tid] += t;
        __syncthreads();
    }
    int inc = s[tid];
    if (i < NN) {
        g_rowptr[i] = sbase + inc - c;
        g_cursor[i] = sbase + inc - c;
    }
    if (i == NN - 1) g_rowptr[NN] = sbase + inc;
}

// ---------------------------------------------------------------------------
// CSR fill + reset g_deg for the next replay
// ---------------------------------------------------------------------------
__global__ void k_fill(const void* __restrict__ ei_raw) {
    int e = blockIdx.x * blockDim.x + threadIdx.x;
    int is64 = block_is64(ei_raw, e);
    if (e < NN) g_deg[e] = 0;
    if (e < NE) {
        int s, d;
        if (is64) {
            const long long* p = (const long long*)ei_raw;
            s = (int)p[e];
            d = (int)p[NE + e];
        } else {
            const int* p = (const int*)ei_raw;
            s = p[e];
            d = p[NE + e];
        }
        if ((unsigned)d < NN && (unsigned)s < NN) {
            int pos = atomicAdd(&g_cursor[d], 1);
            if ((unsigned)pos < NE) g_col[pos] = s;
        }
    }
}

// ---------------------------------------------------------------------------
// FUSED LAYER v2:  out = act( (Anorm @ Xin) @ W + b )
//  - 512 threads (16 warps), 64-row tile, 4 rows per warp -> ~60 regs,
//    2 blocks/SM = 32 warps (occupancy up from 24)
//  - Phase 0: stage W k-pair-packed: wsP[k2][c] = (W[2k2][c], W[2k2+1][c])
//  - Phase 1: warp w aggregates 4 nodes into xs (float4 gathers, shfl bcast)
//  - Phase 2: packed fma.rn.f32x2 along k: per k4 group only
//    6 LDS.64 (w pairs) + 4 LDS.128 (x pairs) + 24 FFMA2
// Xin == nullptr -> read g_hp; outp == nullptr -> write g_hp.
// ---------------------------------------------------------------------------
__global__ void __launch_bounds__(FUSED_T, 2)
k_fused(const float* __restrict__ Xin,
        const float* __restrict__ W,
        const float* __restrict__ bias,
        const float* __restrict__ a1,
        int use_prelu,
        float* __restrict__ outp) {
    extern __shared__ float smem_f[];
    float (*xs)[DD] = (float(*)[DD])smem_f;                          // 24 KB
    unsigned long long (*wsP)[DD] =
        (unsigned long long(*)[DD])(smem_f + XS_FLOATS);             // 36.8 KB

    const float4* x4 = (Xin != nullptr) ? (const float4*)Xin : (const float4*)g_hp;
    float* dst = (outp != nullptr) ? outp : (float*)g_hp;

    int row0 = blockIdx.x * 64;
    int tid  = threadIdx.x;
    int warp = tid >> 5;
    int lane = tid & 31;
    bool activeF = lane < D4;        // 24 lanes carry the 96 features

    // ---- Phase 0: stage W as k-pair-packed f32x2 words ----
#pragma unroll
    for (int i = 0; i < (K2N * DD) / FUSED_T; i++) {     // 9 iters
        int idx = tid + i * FUSED_T;
        int k2 = idx / DD, c = idx % DD;
        unsigned lo = __float_as_uint(W[(2 * k2) * DD + c]);
        unsigned hi = __float_as_uint(W[(2 * k2 + 1) * DD + c]);
        wsP[k2][c] = (unsigned long long)lo | ((unsigned long long)hi << 32);
    }

    // ---------------- Phase 1: aggregate 4 nodes per warp ----------------
#pragma unroll 1
    for (int r = 0; r < 4; r++) {
        int node = row0 + warp * 4 + r;
        float4 acc = make_float4(0.f, 0.f, 0.f, 0.f);
        if (node < NN) {
            float di = g_dinv[node];
            if (activeF) {
                float4 v = x4[node * D4 + lane];
                acc.x = di * v.x; acc.y = di * v.y;
                acc.z = di * v.z; acc.w = di * v.w;
            }
            int beg = g_rowptr[node];
            int end = g_rowptr[node + 1];
            for (int base = beg; base < end; base += 32) {
                int e = base + lane;
                int s = 0;
                float ns = 0.f;
                if (e < end) {
                    s = g_col[e];
                    ns = g_dinv[s];
                }
                int cnt = min(32, end - base);
                int j = 0;
                for (; j + 4 <= cnt; j += 4) {
                    int   s0 = __shfl_sync(0xffffffffu, s,  j + 0);
                    int   s1 = __shfl_sync(0xffffffffu, s,  j + 1);
                    int   s2 = __shfl_sync(0xffffffffu, s,  j + 2);
                    int   s3 = __shfl_sync(0xffffffffu, s,  j + 3);
                    float n0 = __shfl_sync(0xffffffffu, ns, j + 0);
                    float n1 = __shfl_sync(0xffffffffu, ns, j + 1);
                    float n2 = __shfl_sync(0xffffffffu, ns, j + 2);
                    float n3 = __shfl_sync(0xffffffffu, ns, j + 3);
                    if (activeF) {
                        float4 v0 = x4[s0 * D4 + lane];
                        float4 v1 = x4[s1 * D4 + lane];
                        float4 v2 = x4[s2 * D4 + lane];
                        float4 v3 = x4[s3 * D4 + lane];
                        acc.x = fmaf(n0, v0.x, acc.x); acc.y = fmaf(n0, v0.y, acc.y);
                        acc.z = fmaf(n0, v0.z, acc.z); acc.w = fmaf(n0, v0.w, acc.w);
                        acc.x = fmaf(n1, v1.x, acc.x); acc.y = fmaf(n1, v1.y, acc.y);
                        acc.z = fmaf(n1, v1.z, acc.z); acc.w = fmaf(n1, v1.w, acc.w);
                        acc.x = fmaf(n2, v2.x, acc.x); acc.y = fmaf(n2, v2.y, acc.y);
                        acc.z = fmaf(n2, v2.z, acc.z); acc.w = fmaf(n2, v2.w, acc.w);
                        acc.x = fmaf(n3, v3.x, acc.x); acc.y = fmaf(n3, v3.y, acc.y);
                        acc.z = fmaf(n3, v3.z, acc.z); acc.w = fmaf(n3, v3.w, acc.w);
                    }
                }
                for (; j < cnt; j++) {
                    int   sj = __shfl_sync(0xffffffffu, s,  j);
                    float nj = __shfl_sync(0xffffffffu, ns, j);
                    if (activeF) {
                        float4 v = x4[sj * D4 + lane];
                        acc.x = fmaf(nj, v.x, acc.x); acc.y = fmaf(nj, v.y, acc.y);
                        acc.z = fmaf(nj, v.z, acc.z); acc.w = fmaf(nj, v.w, acc.w);
                    }
                }
            }
            acc.x *= di; acc.y *= di; acc.z *= di; acc.w *= di;
        }
        if (activeF)
            *(float4*)&xs[warp * 4 + r][lane * 4] = acc;
    }

    __syncthreads();   // close phases 0+1

    // -------- Phase 2: xs[64][96] @ W via packed f32x2 FMA --------
    int tx = lane;
    int ty = warp;     // rows ty*4 .. ty*4+3

    unsigned long long acc2[4][3];
#pragma unroll
    for (int r = 0; r < 4; r++) { acc2[r][0] = 0ull; acc2[r][1] = 0ull; acc2[r][2] = 0ull; }

#pragma unroll 6
    for (int k4 = 0; k4 < DD; k4 += 4) {
        int k2 = k4 >> 1;
        unsigned long long w00 = wsP[k2][tx];
        unsigned long long w01 = wsP[k2][tx + 32];
        unsigned long long w02 = wsP[k2][tx + 64];
        unsigned long long w10 = wsP[k2 + 1][tx];
        unsigned long long w11 = wsP[k2 + 1][tx + 32];
        unsigned long long w12 = wsP[k2 + 1][tx + 64];
#pragma unroll
        for (int r = 0; r < 4; r++) {
            ulonglong2 a = *(const ulonglong2*)&xs[ty * 4 + r][k4];
            FFMA2(acc2[r][0], a.x, w00);
            FFMA2(acc2[r][1], a.x, w01);
            FFMA2(acc2[r][2], a.x, w02);
            FFMA2(acc2[r][0], a.y, w10);
            FFMA2(acc2[r][1], a.y, w11);
            FFMA2(acc2[r][2], a.y, w12);
        }
    }

    // epilogue: combine halves, bias + optional PReLU, store
    float b0 = bias[tx], b1 = bias[tx + 32], b2 = bias[tx + 64];
    float a = use_prelu ? a1[0] : 0.f;
#pragma unroll
    for (int r = 0; r < 4; r++) {
        int gr = row0 + ty * 4 + r;
        if (gr < NN) {
            float v0 = __uint_as_float((unsigned)acc2[r][0]) +
                       __uint_as_float((unsigned)(acc2[r][0] >> 32)) + b0;
            float v1 = __uint_as_float((unsigned)acc2[r][1]) +
                       __uint_as_float((unsigned)(acc2[r][1] >> 32)) + b1;
            float v2 = __uint_as_float((unsigned)acc2[r][2]) +
                       __uint_as_float((unsigned)(acc2[r][2] >> 32)) + b2;
            if (use_prelu) {
                v0 = v0 > 0.f ? v0 : a * v0;
                v1 = v1 > 0.f ? v1 : a * v1;
                v2 = v2 > 0.f ? v2 : a * v2;
            }
            dst[gr * DD + tx]      = v0;
            dst[gr * DD + tx + 32] = v1;
            dst[gr * DD + tx + 64] = v2;
        }
    }
}

// ---------------------------------------------------------------------------
extern "C" void kernel_launch(void* const* d_in, const int* in_sizes, int n_in,
                              void* d_out, int out_size) {
    const float* x  = (const float*)d_in[0];
    const void*  ei = (const void*)d_in[1];
    const float* W1 = (const float*)d_in[2];
    const float* b1 = (const float*)d_in[3];
    const float* a1 = (const float*)d_in[4];
    const float* W2 = (const float*)d_in[5];
    const float* b2 = (const float*)d_in[6];
    float*       out = (float*)d_out;

    // opt-in to 61.4 KB dynamic smem (host-side, idempotent, capture-safe)
    (void)cudaFuncSetAttribute(k_fused,
                               cudaFuncAttributeMaxDynamicSharedMemorySize,
                               FUSED_SMEM);

    int fusedGrid = (NN + 63) / 64;   // 782

    // launch 0..2: prep
    k_count<<<(NE + 255) / 256, 256>>>(ei);
    k_scan<<<SCAN_NB, SCAN_B>>>();
    k_fill<<<(NE + 255) / 256, 256>>>(ei);

    // launch 3 (PROFILED): layer 1  g_hp = PReLU( (Anorm @ x) @ W1 + b1 )
    k_fused<<<fusedGrid, FUSED_T, FUSED_SMEM>>>(x, W1, b1, a1, 1, nullptr);

    // launch 4: layer 2  out = (Anorm @ g_hp) @ W2 + b2
    k_fused<<<fusedGrid, FUSED_T, FUSED_SMEM>>>(nullptr, W2, b2, a1, 0, out);
}

// round 16
// speedup vs baseline: 1.1430x; 1.0156x over previous
#include <cuda_runtime.h>
#include <cuda_bf16.h>

// Problem constants (fixed shapes from reference)
#define NN 50000
#define NE 800000
#define DD 96
#define D4 (DD / 4)   // 24 float4 per row
#define K2N (DD / 2)  // 48 k-pairs

#define SCAN_B 1024
#define SCAN_NB ((NN + SCAN_B - 1) / SCAN_B)   // 49

// fused-kernel dynamic smem: xs[64][96] f32 + wsP[48][96] f32x2-packed
#define XS_FLOATS (64 * DD)
#define FUSED_SMEM (XS_FLOATS * 4 + K2N * DD * 8)   // 24576 + 36864 = 61440

#define FUSED_T 512   // 16 warps; each warp owns 4 rows

// packed f32x2 FMA: d = a*b + d (elementwise on hi/lo floats)
#define FFMA2(d, a, b) \
    asm("fma.rn.f32x2 %0, %1, %2, %0;" : "+l"(d) : "l"(a), "l"(b))

// ---- device scratch (no runtime allocation allowed) ----
// g_deg holds pure in-edge counts. Zero on first use (.bss); k_fill re-zeroes
// it each call so every graph replay starts from zero.
__device__ int   g_deg[NN];
__device__ float g_dinv[NN];
__device__ int   g_rowptr[NN + 1];
__device__ int   g_cursor[NN];
__device__ int2  g_ecol[NE];      // CSR payload: {src, bitcast(dinv[src])}
__device__ float g_hp[NN * DD];   // layer-1 output (post bias+PReLU)

// ---------------------------------------------------------------------------
// Block-local edge-dtype vote (int64 vs silently-int32 edge_index).
// ---------------------------------------------------------------------------
__device__ __forceinline__ int block_is64(const void* ei_raw, int e) {
    const long long* p64 = (const long long*)ei_raw;
    int bad = 0;
    if (e < NE) {
        long long v = p64[e];
        if (v < 0 || v >= NN) bad = 1;
    }
    return !__syncthreads_or(bad);
}

// ---------------------------------------------------------------------------
// degree count (dst half only)
// ---------------------------------------------------------------------------
__global__ void k_count(const void* __restrict__ ei_raw) {
    int e = blockIdx.x * blockDim.x + threadIdx.x;
    int is64 = block_is64(ei_raw, e);
    if (e < NE) {
        int d = is64 ? (int)((const long long*)ei_raw)[NE + e]
                     : ((const int*)ei_raw)[NE + e];
        if ((unsigned)d < NN) atomicAdd(&g_deg[d], 1);
    }
}

// ---------------------------------------------------------------------------
// single-kernel scan + dinv (g_deg read-only here)
// ---------------------------------------------------------------------------
__global__ void k_scan() {
    __shared__ int s[SCAN_B];
    __shared__ int sbase;
    int bid = blockIdx.x;
    int tid = threadIdx.x;

    int pre = 0;
    for (int i = tid; i < bid * SCAN_B; i += SCAN_B) pre += g_deg[i];
    s[tid] = pre;
    __syncthreads();
    for (int off = SCAN_B / 2; off > 0; off >>= 1) {
        if (tid < off) s[tid] += s[tid + off];
        __syncthreads();
    }
    if (tid == 0) sbase = s[0];
    __syncthreads();

    int i = bid * SCAN_B + tid;
    int c = (i < NN) ? g_deg[i] : 0;
    if (i < NN) g_dinv[i] = rsqrtf((float)(c + 1));   // +1 = self loop
    s[tid] = c;
    __syncthreads();
    for (int off = 1; off < SCAN_B; off <<= 1) {
        int t = 0;
        if (tid >= off) t = s[tid - off];
        __syncthreads();
        s[tid] += t;
        __syncthreads();
    }
    int inc = s[tid];
    if (i < NN) {
        g_rowptr[i] = sbase + inc - c;
        g_cursor[i] = sbase + inc - c;
    }
    if (i == NN - 1) g_rowptr[NN] = sbase + inc;
}

// ---------------------------------------------------------------------------
// CSR fill: writes {src, dinv[src]} pairs (dinv ready after k_scan), and
// resets g_deg for the next replay.
// ---------------------------------------------------------------------------
__global__ void k_fill(const void* __restrict__ ei_raw) {
    int e = blockIdx.x * blockDim.x + threadIdx.x;
    int is64 = block_is64(ei_raw, e);
    if (e < NN) g_deg[e] = 0;
    if (e < NE) {
        int s, d;
        if (is64) {
            const long long* p = (const long long*)ei_raw;
            s = (int)p[e];
            d = (int)p[NE + e];
        } else {
            const int* p = (const int*)ei_raw;
            s = p[e];
            d = p[NE + e];
        }
        if ((unsigned)d < NN && (unsigned)s < NN) {
            int pos = atomicAdd(&g_cursor[d], 1);
            if ((unsigned)pos < NE)
                g_ecol[pos] = make_int2(s, __float_as_int(g_dinv[s]));
        }
    }
}

// ---------------------------------------------------------------------------
// FUSED LAYER v3:  out = act( (Anorm @ Xin) @ W + b )
//  - Phase 0: stage W k-pair-packed for f32x2 FMA
//  - Phase 1: warp aggregates 4 nodes; CSR payload is pre-packed (col,dinv)
//    -> ONE coalesced LDG.64 per chunk (no scattered dinv gather);
//    rowptr for all 4 nodes fetched in one batched LDG + shuffles
//  - Phase 2: packed fma.rn.f32x2 (unchanged from v2)
// Xin == nullptr -> read g_hp; outp == nullptr -> write g_hp.
// ---------------------------------------------------------------------------
__global__ void __launch_bounds__(FUSED_T, 2)
k_fused(const float* __restrict__ Xin,
        const float* __restrict__ W,
        const float* __restrict__ bias,
        const float* __restrict__ a1,
        int use_prelu,
        float* __restrict__ outp) {
    extern __shared__ float smem_f[];
    float (*xs)[DD] = (float(*)[DD])smem_f;                          // 24 KB
    unsigned long long (*wsP)[DD] =
        (unsigned long long(*)[DD])(smem_f + XS_FLOATS);             // 36.8 KB

    const float4* x4 = (Xin != nullptr) ? (const float4*)Xin : (const float4*)g_hp;
    float* dst = (outp != nullptr) ? outp : (float*)g_hp;

    int row0 = blockIdx.x * 64;
    int tid  = threadIdx.x;
    int warp = tid >> 5;
    int lane = tid & 31;
    bool activeF = lane < D4;        // 24 lanes carry the 96 features

    // ---- Phase 0: stage W as k-pair-packed f32x2 words ----
#pragma unroll
    for (int i = 0; i < (K2N * DD) / FUSED_T; i++) {     // 9 iters
        int idx = tid + i * FUSED_T;
        int k2 = idx / DD, c = idx % DD;
        unsigned lo = __float_as_uint(W[(2 * k2) * DD + c]);
        unsigned hi = __float_as_uint(W[(2 * k2 + 1) * DD + c]);
        wsP[k2][c] = (unsigned long long)lo | ((unsigned long long)hi << 32);
    }

    // ---- batched rowptr fetch: lanes 0..4 load rowptr[n0..n0+4] ----
    int n0 = row0 + warp * 4;
    int rp = 0;
    if (lane < 5) {
        int idx = n0 + lane;
        if (idx > NN) idx = NN;
        rp = g_rowptr[idx];
    }

    // ---------------- Phase 1: aggregate 4 nodes per warp ----------------
#pragma unroll 1
    for (int r = 0; r < 4; r++) {
        int node = n0 + r;
        int beg = __shfl_sync(0xffffffffu, rp, r);
        int end = __shfl_sync(0xffffffffu, rp, r + 1);
        float4 acc = make_float4(0.f, 0.f, 0.f, 0.f);
        if (node < NN) {
            float di = g_dinv[node];
            if (activeF) {
                float4 v = x4[node * D4 + lane];
                acc.x = di * v.x; acc.y = di * v.y;
                acc.z = di * v.z; acc.w = di * v.w;
            }
            for (int base = beg; base < end; base += 32) {
                int e = base + lane;
                int s = 0;
                float ns = 0.f;
                if (e < end) {
                    int2 cn = g_ecol[e];           // one coalesced LDG.64
                    s = cn.x;
                    ns = __int_as_float(cn.y);
                }
                int cnt = min(32, end - base);
                int j = 0;
                for (; j + 4 <= cnt; j += 4) {
                    int   s0 = __shfl_sync(0xffffffffu, s,  j + 0);
                    int   s1 = __shfl_sync(0xffffffffu, s,  j + 1);
                    int   s2 = __shfl_sync(0xffffffffu, s,  j + 2);
                    int   s3 = __shfl_sync(0xffffffffu, s,  j + 3);
                    float n0f = __shfl_sync(0xffffffffu, ns, j + 0);
                    float n1f = __shfl_sync(0xffffffffu, ns, j + 1);
                    float n2f = __shfl_sync(0xffffffffu, ns, j + 2);
                    float n3f = __shfl_sync(0xffffffffu, ns, j + 3);
                    if (activeF) {
                        float4 v0 = x4[s0 * D4 + lane];
                        float4 v1 = x4[s1 * D4 + lane];
                        float4 v2 = x4[s2 * D4 + lane];
                        float4 v3 = x4[s3 * D4 + lane];
                        acc.x = fmaf(n0f, v0.x, acc.x); acc.y = fmaf(n0f, v0.y, acc.y);
                        acc.z = fmaf(n0f, v0.z, acc.z); acc.w = fmaf(n0f, v0.w, acc.w);
                        acc.x = fmaf(n1f, v1.x, acc.x); acc.y = fmaf(n1f, v1.y, acc.y);
                        acc.z = fmaf(n1f, v1.z, acc.z); acc.w = fmaf(n1f, v1.w, acc.w);
                        acc.x = fmaf(n2f, v2.x, acc.x); acc.y = fmaf(n2f, v2.y, acc.y);
                        acc.z = fmaf(n2f, v2.z, acc.z); acc.w = fmaf(n2f, v2.w, acc.w);
                        acc.x = fmaf(n3f, v3.x, acc.x); acc.y = fmaf(n3f, v3.y, acc.y);
                        acc.z = fmaf(n3f, v3.z, acc.z); acc.w = fmaf(n3f, v3.w, acc.w);
                    }
                }
                for (; j < cnt; j++) {
                    int   sj = __shfl_sync(0xffffffffu, s,  j);
                    float nj = __shfl_sync(0xffffffffu, ns, j);
                    if (activeF) {
                        float4 v = x4[sj * D4 + lane];
                        acc.x = fmaf(nj, v.x, acc.x); acc.y = fmaf(nj, v.y, acc.y);
                        acc.z = fmaf(nj, v.z, acc.z); acc.w = fmaf(nj, v.w, acc.w);
                    }
                }
            }
            acc.x *= di; acc.y *= di; acc.z *= di; acc.w *= di;
        }
        if (activeF)
            *(float4*)&xs[warp * 4 + r][lane * 4] = acc;
    }

    __syncthreads();   // close phases 0+1

    // -------- Phase 2: xs[64][96] @ W via packed f32x2 FMA --------
    int tx = lane;
    int ty = warp;     // rows ty*4 .. ty*4+3

    unsigned long long acc2[4][3];
#pragma unroll
    for (int r = 0; r < 4; r++) { acc2[r][0] = 0ull; acc2[r][1] = 0ull; acc2[r][2] = 0ull; }

#pragma unroll 6
    for (int k4 = 0; k4 < DD; k4 += 4) {
        int k2 = k4 >> 1;
        unsigned long long w00 = wsP[k2][tx];
        unsigned long long w01 = wsP[k2][tx + 32];
        unsigned long long w02 = wsP[k2][tx + 64];
        unsigned long long w10 = wsP[k2 + 1][tx];
        unsigned long long w11 = wsP[k2 + 1][tx + 32];
        unsigned long long w12 = wsP[k2 + 1][tx + 64];
#pragma unroll
        for (int r = 0; r < 4; r++) {
            ulonglong2 a = *(const ulonglong2*)&xs[ty * 4 + r][k4];
            FFMA2(acc2[r][0], a.x, w00);
            FFMA2(acc2[r][1], a.x, w01);
            FFMA2(acc2[r][2], a.x, w02);
            FFMA2(acc2[r][0], a.y, w10);
            FFMA2(acc2[r][1], a.y, w11);
            FFMA2(acc2[r][2], a.y, w12);
        }
    }

    // epilogue: combine halves, bias + optional PReLU, store
    float b0 = bias[tx], b1 = bias[tx + 32], b2 = bias[tx + 64];
    float a = use_prelu ? a1[0] : 0.f;
#pragma unroll
    for (int r = 0; r < 4; r++) {
        int gr = row0 + ty * 4 + r;
        if (gr < NN) {
            float v0 = __uint_as_float((unsigned)acc2[r][0]) +
                       __uint_as_float((unsigned)(acc2[r][0] >> 32)) + b0;
            float v1 = __uint_as_float((unsigned)acc2[r][1]) +
                       __uint_as_float((unsigned)(acc2[r][1] >> 32)) + b1;
            float v2 = __uint_as_float((unsigned)acc2[r][2]) +
                       __uint_as_float((unsigned)(acc2[r][2] >> 32)) + b2;
            if (use_prelu) {
                v0 = v0 > 0.f ? v0 : a * v0;
                v1 = v1 > 0.f ? v1 : a * v1;
                v2 = v2 > 0.f ? v2 : a * v2;
            }
            dst[gr * DD + tx]      = v0;
            dst[gr * DD + tx + 32] = v1;
            dst[gr * DD + tx + 64] = v2;
        }
    }
}

// ---------------------------------------------------------------------------
extern "C" void kernel_launch(void* const* d_in, const int* in_sizes, int n_in,
                              void* d_out, int out_size) {
    const float* x  = (const float*)d_in[0];
    const void*  ei = (const void*)d_in[1];
    const float* W1 = (const float*)d_in[2];
    const float* b1 = (const float*)d_in[3];
    const float* a1 = (const float*)d_in[4];
    const float* W2 = (const float*)d_in[5];
    const float* b2 = (const float*)d_in[6];
    float*       out = (float*)d_out;

    // opt-in to 61.4 KB dynamic smem (host-side, idempotent, capture-safe)
    (void)cudaFuncSetAttribute(k_fused,
                               cudaFuncAttributeMaxDynamicSharedMemorySize,
                               FUSED_SMEM);

    int fusedGrid = (NN + 63) / 64;   // 782

    // launch 0..2: prep
    k_count<<<(NE + 255) / 256, 256>>>(ei);
    k_scan<<<SCAN_NB, SCAN_B>>>();
    k_fill<<<(NE + 255) / 256, 256>>>(ei);

    // launch 3 (PROFILED): layer 1  g_hp = PReLU( (Anorm @ x) @ W1 + b1 )
    k_fused<<<fusedGrid, FUSED_T, FUSED_SMEM>>>(x, W1, b1, a1, 1, nullptr);

    // launch 4: layer 2  out = (Anorm @ g_hp) @ W2 + b2
    k_fused<<<fusedGrid, FUSED_T, FUSED_SMEM>>>(nullptr, W2, b2, a1, 0, out);
}